// round 15
// baseline (speedup 1.0000x reference)
#include <cuda_runtime.h>
#include <math.h>

#define BB 8
#define CC 512
#define NN 19
#define HW 16384
#define TOTPX (BB*HW)
#define NCH3 32   /* ocr pixel-chunks per batch */

typedef unsigned long long ull;

// ---------------- scratch (device globals; no allocation) ----------------
__device__ float g_pre[(size_t)BB*NN*HW];        // pre-softmax logits [B,N,HW]
__device__ float g_rowmax[BB*NN];
__device__ float g_rowinv[BB*NN];                // 1/sum(exp)
__device__ float g_part[(size_t)BB*NCH3*NN*CC];  // ocr partials per chunk
__device__ float g_ocr[(size_t)BB*NN*CC];        // reduced ocr
__device__ float g_weff[(size_t)BB*CC*20];       // fin_w*(1+gate), layout [b][c][20]
__device__ int   g_dummy;

__device__ __forceinline__ void fma2(ull& acc, ull a, ull b){
    asm("fma.rn.f32x2 %0, %1, %2, %0;" : "+l"(acc) : "l"(a), "l"(b));
}
__device__ __forceinline__ ull pk(float a, float b){
    ull r;
    asm("mov.b64 %0, {%1, %2};" : "=l"(r) : "r"(__float_as_uint(a)), "r"(__float_as_uint(b)));
    return r;
}
__device__ __forceinline__ float2 upk(ull v){
    unsigned int lo, hi;
    asm("mov.b64 {%0, %1}, %2;" : "=r"(lo), "=r"(hi) : "l"(v));
    float2 r; r.x = __uint_as_float(lo); r.y = __uint_as_float(hi); return r;
}
__device__ __forceinline__ unsigned smem_u32(const void* p){
    unsigned r;
    asm("{ .reg .u64 t; cvta.to.shared.u64 t, %1; cvt.u32.u64 %0, t; }" : "=r"(r) : "l"(p));
    return r;
}
__device__ __forceinline__ float sg(float v){ return 1.f/(1.f+__expf(-v)); }
__device__ __forceinline__ float chainf(float m, float dl, float bl){
    float d  = dl * sg(m);
    float bd = bl * sg(d);
    d += sg(bd);
    return m + sg(d);
}

// ---------------- dummy: shifts k3 into ncu's captured (4th) slot ----------------
__global__ void knop(int v){ if (threadIdx.x == 9999) g_dummy = v; }

// ---------------- K1 (measured 211µs): quad-split + 4px + prefetch + pointer-bump ----------------
__global__ void __launch_bounds__(512, 1) k1(const float* __restrict__ x,
    const float* __restrict__ mw, const float* __restrict__ mb,
    const float* __restrict__ dw, const float* __restrict__ db,
    const float* __restrict__ bw, const float* __restrict__ bbias)
{
    extern __shared__ float sm[];
    float* ws = sm;            // [512][64]: c-major, 4 chunks of 16 per channel
    float* bs = sm + CC*64;    // [64]
    int tid = threadIdx.x;
    for (int i = tid; i < CC*64; i += 512){
        int c = i >> 6, r = i & 63;
        int q = r >> 4, j = r & 15;
        int ii = j/3, k = j - 3*ii;
        int niq = (q < 3) ? 5 : 4;
        float v = 0.f;
        if (ii < niq && j < 15){
            int n = q*5 + ii;
            v = (k == 0) ? mw[n*CC + c] : (k == 1) ? dw[n*CC + c] : bw[n*CC + c];
        }
        ws[i] = v;
    }
    if (tid < 64){
        int q = tid >> 4, j = tid & 15;
        int ii = j/3, k = j - 3*ii;
        int niq = (q < 3) ? 5 : 4;
        float v = 0.f;
        if (ii < niq && j < 15){
            int n = q*5 + ii;
            v = (k == 0) ? mb[n] : (k == 1) ? db[n] : bbias[n];
        }
        bs[tid] = v;
    }
    __syncthreads();

    const int PER = 888;
    int start = blockIdx.x * PER;
    int end = min(start + PER, TOTPX);
    int wid = tid >> 5, lane = tid & 31;
    int g = wid >> 2, q = wid & 3;
    int niq = (q < 3) ? 5 : 4;
    const float* wq = ws + q*16;
    const float* bq = bs + q*16;

    for (int base = start; base < end; base += 512){
        int gp0 = base + g*128 + 4*lane;          // 4-aligned
        bool any = (gp0 < end);
        int gpc = any ? gp0 : start;
        int b = gpc >> 14, p = gpc & (HW-1);
        const float4* xq = reinterpret_cast<const float4*>(x + (size_t)b*CC*HW + p);
        ull A[32];                                 // [pair 0..7][px 0..3]
        #pragma unroll
        for (int j = 0; j < 32; j++) A[j] = 0ull;

        float4 xbuf[4];
        #pragma unroll
        for (int k = 0; k < 4; k++) xbuf[k] = __ldg(xq + k*4096);
        xq += 4*4096;

        const float* wc = wq;
        #pragma unroll 1
        for (int c0 = 0; c0 < CC; c0 += 4){
            bool pf = (c0 + 4 < CC);
            #pragma unroll
            for (int k = 0; k < 4; k++){
                float4 xv = xbuf[k];
                if (pf) xbuf[k] = __ldg(xq + k*4096);
                ull xd[4];
                xd[0] = pk(xv.x, xv.x); xd[1] = pk(xv.y, xv.y);
                xd[2] = pk(xv.z, xv.z); xd[3] = pk(xv.w, xv.w);
                const ulonglong2* wr = reinterpret_cast<const ulonglong2*>(wc + k*64);
                #pragma unroll
                for (int j = 0; j < 4; j++){
                    ulonglong2 w = wr[j];
                    #pragma unroll
                    for (int px = 0; px < 4; px++){
                        fma2(A[(2*j)*4 + px],   w.x, xd[px]);
                        fma2(A[(2*j+1)*4 + px], w.y, xd[px]);
                    }
                }
            }
            xq += 4*4096;
            wc += 4*64;
        }
        if (any){
            size_t ob = (size_t)b*NN*HW + p;
            #pragma unroll
            for (int i = 0; i < 5; i++){
                if (i < niq){
                    int n = q*5 + i;
                    int sm_ = 3*i, sd_ = 3*i+1, sb_ = 3*i+2;
                    float bm = bq[sm_], bd = bq[sd_], bb = bq[sb_];
                    float vout[4];
                    #pragma unroll
                    for (int px = 0; px < 4; px++){
                        float2 fm = upk(A[(sm_>>1)*4 + px]);
                        float2 fd = upk(A[(sd_>>1)*4 + px]);
                        float2 fbv = upk(A[(sb_>>1)*4 + px]);
                        float m = ((sm_&1) ? fm.y : fm.x) + bm;
                        float d = ((sd_&1) ? fd.y : fd.x) + bd;
                        float bv = ((sb_&1) ? fbv.y : fbv.x) + bb;
                        vout[px] = chainf(m, d, bv);
                    }
                    float* dst = g_pre + ob + (size_t)n*HW;
                    *reinterpret_cast<float4*>(dst) = make_float4(vout[0], vout[1], vout[2], vout[3]);
                }
            }
        }
    }
}

// ---------------- K2 v3 (measured 6.4µs): single-pass exp-sum ----------------
__global__ void __launch_bounds__(512) k2(){
    __shared__ float red[512];
    int row = blockIdx.x, tid = threadIdx.x;
    const float4* base = reinterpret_cast<const float4*>(g_pre + (size_t)row*HW);
    float sum = 0.f;
    #pragma unroll 4
    for (int i = tid; i < HW/4; i += 512){
        float4 v = base[i];
        sum += __expf(v.x) + __expf(v.y) + __expf(v.z) + __expf(v.w);
    }
    red[tid] = sum; __syncthreads();
    for (int s = 256; s > 0; s >>= 1){ if (tid < s) red[tid] += red[tid+s]; __syncthreads(); }
    if (tid == 0){ g_rowmax[row] = 0.f; g_rowinv[row] = 1.f/red[0]; }
}

// ---------------- K3 v7: 4-deep cp.async ring, 8-px tiles, px-pair lanes ----------------
// grid B*32 x 256 thr (2 CTAs/SM). Thread owns channels (tid, tid+256).
// x tiles [512c][10] c-major, ring of 4; wait_group 2 keeps 3 fills in flight.
// Prob pairs prefetched 3 tiles ahead (LDG before compute, exp+STS after).
#define XR7 10
#define TPX7 8
#define NT7 64
#define DEP7 4
__global__ void __launch_bounds__(256, 2) k3(const float* __restrict__ x){
    extern __shared__ float smem3[];
    ull* ppb = (ull*)(smem3 + DEP7*CC*XR7);      // [4][80]
    __shared__ float rm[NN], ri[NN];
    int tid = threadIdx.x;
    int b = blockIdx.x >> 5;
    int chunk = blockIdx.x & 31;
    int p0 = chunk * 512;
    if (tid < NN){ rm[tid] = g_rowmax[b*NN+tid]; ri[tid] = g_rowinv[b*NN+tid]; }
    const float* xb = x     + (size_t)b*CC*HW + p0;
    const float* pb = g_pre + (size_t)b*NN*HW + p0;
    int c0 = tid, c1 = tid + 256;
    int ppx = tid/20, ppn = tid%20;              // prob role: tid<80
    bool probrole = (tid < 80) && (ppn < NN);
    unsigned xs_s[DEP7];
    #pragma unroll
    for (int d = 0; d < DEP7; d++) xs_s[d] = smem_u32(smem3 + d*CC*XR7);
    ull acc0[20], acc1[20];
    #pragma unroll
    for (int n = 0; n < 20; n++){ acc0[n] = 0ull; acc1[n] = 0ull; }
    __syncthreads();                              // rm/ri visible

    // x-fill tile T into ring slot BUF: 8 x 8B cp.async per thread (16 KB tile)
    #define XFILL(T, BUF) do {                                             \
        int tp_ = (T)*TPX7;                                                \
        _Pragma("unroll")                                                  \
        for (int k_ = 0; k_ < 8; k_++){                                    \
            int i_ = tid + k_*256;                                         \
            int cc_ = i_ >> 2, px2_ = (i_ & 3) * 2;                        \
            const float* src_ = xb + (size_t)cc_*HW + tp_ + px2_;          \
            unsigned dst_ = xs_s[BUF] + (unsigned)((cc_*XR7 + px2_)*4);    \
            asm volatile("cp.async.ca.shared.global [%0], [%1], 8;"        \
                         :: "r"(dst_), "l"(src_) : "memory");              \
        }                                                                  \
        asm volatile("cp.async.commit_group;" ::: "memory");               \
    } while(0)

    // prologue: 3 tiles in flight
    XFILL(0, 0); XFILL(1, 1); XFILL(2, 2);
    if (probrole){
        #pragma unroll
        for (int tt = 0; tt < 3; tt++){
            float2 pr = *reinterpret_cast<const float2*>(pb + (size_t)ppn*HW + tt*TPX7 + 2*ppx);
            ppb[tt*80 + tid] = pk(__expf(pr.x - rm[ppn])*ri[ppn], __expf(pr.y - rm[ppn])*ri[ppn]);
        }
    }
    asm volatile("cp.async.wait_group 2;" ::: "memory");   // tile 0 resident
    __syncthreads();

    #pragma unroll 1
    for (int t = 0; t < NT7; t++){
        int buf = t & 3;
        float2 prnext = make_float2(0.f, 0.f);
        bool havenext = (t + 3 < NT7);
        if (havenext){
            XFILL(t+3, (t+3)&3);
            if (probrole)
                prnext = *reinterpret_cast<const float2*>(pb + (size_t)ppn*HW + (t+3)*TPX7 + 2*ppx);
        }
        const float* xs = smem3 + buf*CC*XR7;
        const ull* pp = ppb + buf*80;
        #pragma unroll
        for (int pxp = 0; pxp < 4; pxp++){
            ull xx0 = *reinterpret_cast<const ull*>(&xs[c0*XR7 + 2*pxp]);
            ull xx1 = *reinterpret_cast<const ull*>(&xs[c1*XR7 + 2*pxp]);
            const ulonglong2* pr = reinterpret_cast<const ulonglong2*>(&pp[pxp*20]);
            #pragma unroll
            for (int j = 0; j < 10; j++){
                ulonglong2 w = pr[j];
                fma2(acc0[2*j],   w.x, xx0); fma2(acc0[2*j+1], w.y, xx0);
                fma2(acc1[2*j],   w.x, xx1); fma2(acc1[2*j+1], w.y, xx1);
            }
        }
        if (havenext && probrole)
            ppb[((t+3)&3)*80 + tid] =
                pk(__expf(prnext.x - rm[ppn])*ri[ppn], __expf(prnext.y - rm[ppn])*ri[ppn]);
        asm volatile("cp.async.wait_group 2;" ::: "memory");  // next tile resident
        __syncthreads();
    }
    #undef XFILL
    float* outp = g_part + (size_t)blockIdx.x*(NN*CC);
    #pragma unroll
    for (int n = 0; n < NN; n++){
        float2 v0 = upk(acc0[n]), v1 = upk(acc1[n]);
        outp[n*CC + c0] = v0.x + v0.y;   // even-px + odd-px partials
        outp[n*CC + c1] = v1.x + v1.y;
    }
}

// ---------------- K4a (measured 6.8µs): reduce ocr partials ----------------
__global__ void __launch_bounds__(512) k4a(){
    int b = blockIdx.x / NN, n = blockIdx.x % NN, c = threadIdx.x;
    float s = 0.f;
    #pragma unroll 8
    for (int ch = 0; ch < NCH3; ch++)
        s += g_part[((size_t)(b*NCH3 + ch))*(NN*CC) + n*CC + c];
    g_ocr[((size_t)b*NN + n)*CC + c] = s;
}

// ---------------- block sum helper ----------------
__device__ __forceinline__ float blockSum(float v, float* red, int tid){
    __syncthreads();
    #pragma unroll
    for (int o = 16; o; o >>= 1) v += __shfl_xor_sync(0xffffffffu, v, o);
    if ((tid & 31) == 0) red[tid >> 5] = v;
    __syncthreads();
    if (tid < 32){
        float r = (tid < 16) ? red[tid] : 0.f;
        #pragma unroll
        for (int o = 8; o; o >>= 1) r += __shfl_xor_sync(0xffffffffu, r, o);
        if (tid == 0) red[0] = r;
    }
    __syncthreads();
    return red[0];
}

// ---------------- K4b: att pool + MLP gate -> g_weff ----------------
__global__ void __launch_bounds__(512) k4b(
    const float* __restrict__ mask_w, const float* __restrict__ mask_b,
    const float* __restrict__ cm1_w,  const float* __restrict__ cm1_b,
    const float* __restrict__ ln_g,   const float* __restrict__ ln_b,
    const float* __restrict__ cm2_w,  const float* __restrict__ cm2_b,
    const float* __restrict__ fin_w)
{
    __shared__ float ocr[NN][CC];
    __shared__ float mws[CC];
    __shared__ float ctx[CC];
    __shared__ float h[CC];
    __shared__ float attw[NN];
    __shared__ float red[16];
    __shared__ float stat[2];
    int b = blockIdx.x, tid = threadIdx.x;
    int wid = tid >> 5, lane = tid & 31;
    mws[tid] = mask_w[tid];
    for (int n = 0; n < NN; n++)
        ocr[n][tid] = g_ocr[((size_t)b*NN + n)*CC + tid];
    __syncthreads();
    for (int n = wid; n < NN; n += 16){
        float s = 0.f;
        #pragma unroll
        for (int l = lane; l < CC; l += 32) s += ocr[n][l]*mws[l];
        #pragma unroll
        for (int o = 16; o; o >>= 1) s += __shfl_xor_sync(0xffffffffu, s, o);
        if (lane == 0) attw[n] = s;
    }
    __syncthreads();
    if (tid == 0){
        float mbv = mask_b[0];
        float amax = -3.4e38f;
        for (int n = 0; n < NN; n++) amax = fmaxf(amax, attw[n] + mbv);
        float s = 0.f;
        for (int n = 0; n < NN; n++){ float e = __expf(attw[n] + mbv - amax); attw[n] = e; s += e; }
        float inv = 1.f/s;
        for (int n = 0; n < NN; n++) attw[n] *= inv;
    }
    __syncthreads();
    float cv = 0.f;
    #pragma unroll
    for (int n = 0; n < NN; n++) cv += ocr[n][tid]*attw[n];
    ctx[tid] = cv; __syncthreads();
    float acc = cm1_b[tid];
    {
        const float4* w1 = reinterpret_cast<const float4*>(cm1_w + (size_t)tid*CC);
        const float4* cx = reinterpret_cast<const float4*>(ctx);
        #pragma unroll 4
        for (int q = 0; q < CC/4; q++){
            float4 wv = __ldg(w1 + q); float4 xv = cx[q];
            acc += wv.x*xv.x + wv.y*xv.y + wv.z*xv.z + wv.w*xv.w;
        }
    }
    float mu = blockSum(acc, red, tid) * (1.f/CC);
    if (tid == 0) stat[0] = mu;
    float dv = acc - mu;
    float var = blockSum(dv*dv, red, tid) * (1.f/CC);
    float tt = dv*rsqrtf(var + 1e-5f)*ln_g[tid] + ln_b[tid];
    h[tid] = fmaxf(tt, 0.f);
    __syncthreads();
    float acc2 = cm2_b[tid];
    {
        const float4* w2 = reinterpret_cast<const float4*>(cm2_w + (size_t)tid*CC);
        const float4* hh = reinterpret_cast<const float4*>(h);
        #pragma unroll 4
        for (int q = 0; q < CC/4; q++){
            float4 wv = __ldg(w2 + q); float4 xv = hh[q];
            acc2 += wv.x*xv.x + wv.y*xv.y + wv.z*xv.z + wv.w*xv.w;
        }
    }
    float scale = 1.f + 1.f/(1.f+__expf(-acc2));   // 1 + gate
    float* wo = g_weff + (size_t)b*CC*20 + (size_t)tid*20;
    #pragma unroll
    for (int n = 0; n < NN; n++) wo[n] = fin_w[n*CC + tid]*scale;
    wo[19] = 0.f;
}

// ---------------- K5 v4b: warp-pair n-split, 4 px/thread, 8-deep prefetch ----------------
__global__ void __launch_bounds__(256, 2) k5(const float* __restrict__ x,
                                             const float* __restrict__ fin_b,
                                             float* __restrict__ out)
{
    extern __shared__ float sm5[];
    float* ws5 = sm5;             // [512][24]
    float* fbs = sm5 + CC*24;     // [24]
    int tid = threadIdx.x;
    int b = blockIdx.x >> 5;
    int chunk = blockIdx.x & 31;
    const float* wsrc = g_weff + (size_t)b*CC*20;
    for (int i = tid; i < CC*24; i += 256){
        int c = i/24, r = i%24;
        int h = r/12, j = r%12;
        int n = 10*h + j;
        ws5[i] = (j < 10 && n < 19) ? wsrc[c*20 + n] : 0.f;
    }
    if (tid < 24) fbs[tid] = (tid < 19) ? fin_b[tid] : 0.f;
    __syncthreads();

    int wid = tid >> 5, lane = tid & 31;
    int u = wid >> 1, h = wid & 1;
    int p = chunk*512 + u*128 + 4*lane;
    const float4* xq = reinterpret_cast<const float4*>(x + (size_t)b*CC*HW + p);
    ull acc[20];                                   // [pair 0..4][px 0..3]
    #pragma unroll
    for (int j = 0; j < 20; j++) acc[j] = 0ull;

    float4 xbuf[8];
    #pragma unroll
    for (int k = 0; k < 8; k++) xbuf[k] = __ldg(xq + k*4096);
    xq += 8*4096;

    const float* wc = ws5 + h*12;
    #pragma unroll 1
    for (int c0 = 0; c0 < CC; c0 += 8){
        bool pf = (c0 + 8 < CC);
        #pragma unroll
        for (int k = 0; k < 8; k++){
            float4 xv = xbuf[k];
            if (pf) xbuf[k] = __ldg(xq + k*4096);
            ull xd[4];
            xd[0] = pk(xv.x, xv.x); xd[1] = pk(xv.y, xv.y);
            xd[2] = pk(xv.z, xv.z); xd[3] = pk(xv.w, xv.w);
            const ulonglong2* wr = reinterpret_cast<const ulonglong2*>(wc + k*24);
            ulonglong2 w01 = wr[0];
            ulonglong2 w23 = wr[1];
            ulonglong2 w45 = wr[2];
            #pragma unroll
            for (int px = 0; px < 4; px++){
                fma2(acc[0*4 + px], w01.x, xd[px]);
                fma2(acc[1*4 + px], w01.y, xd[px]);
                fma2(acc[2*4 + px], w23.x, xd[px]);
                fma2(acc[3*4 + px], w23.y, xd[px]);
                fma2(acc[4*4 + px], w45.x, xd[px]);
            }
        }
        xq += 8*4096;
        wc += 8*24;
    }
    size_t ob = (size_t)b*NN*HW + p;
    #pragma unroll
    for (int pj = 0; pj < 5; pj++){
        int n0 = 10*h + 2*pj, n1 = n0 + 1;
        float v0[4], v1[4];
        #pragma unroll
        for (int px = 0; px < 4; px++){
            float2 f = upk(acc[pj*4 + px]);
            v0[px] = f.x + fbs[n0];
            v1[px] = f.y + ((n1 < 19) ? fbs[n1] : 0.f);
        }
        *reinterpret_cast<float4*>(out + ob + (size_t)n0*HW) = make_float4(v0[0], v0[1], v0[2], v0[3]);
        if (n1 < 19)
            *reinterpret_cast<float4*>(out + ob + (size_t)n1*HW) = make_float4(v1[0], v1[1], v1[2], v1[3]);
    }
}

extern "C" void kernel_launch(void* const* d_in, const int* in_sizes, int n_in,
                              void* d_out, int out_size) {
    const float* x      = (const float*)d_in[0];
    const float* map_w  = (const float*)d_in[1];
    const float* map_b  = (const float*)d_in[2];
    const float* dist_w = (const float*)d_in[3];
    const float* dist_b = (const float*)d_in[4];
    const float* bnd_w  = (const float*)d_in[5];
    const float* bnd_b  = (const float*)d_in[6];
    const float* mask_w = (const float*)d_in[7];
    const float* mask_b = (const float*)d_in[8];
    const float* cm1_w  = (const float*)d_in[9];
    const float* cm1_b  = (const float*)d_in[10];
    const float* ln_g   = (const float*)d_in[11];
    const float* ln_b   = (const float*)d_in[12];
    const float* cm2_w  = (const float*)d_in[13];
    const float* cm2_b  = (const float*)d_in[14];
    const float* fin_w  = (const float*)d_in[15];
    const float* fin_b  = (const float*)d_in[16];
    float* out = (float*)d_out;

    const int K1_SMEM = (CC*64 + 64)*4;                        // 131328 B
    const int K3_SMEM = (DEP7*CC*XR7)*4 + DEP7*80*8;           // 84480 B
    const int K5_SMEM = (CC*24 + 24)*4;                        // 49248 B
    cudaFuncSetAttribute(k1, cudaFuncAttributeMaxDynamicSharedMemorySize, K1_SMEM);
    cudaFuncSetAttribute(k3, cudaFuncAttributeMaxDynamicSharedMemorySize, K3_SMEM);
    cudaFuncSetAttribute(k5, cudaFuncAttributeMaxDynamicSharedMemorySize, K5_SMEM);

    // one no-op: k3 lands in ncu's captured (4th) launch slot
    knop<<<1, 32>>>(0);

    k1<<<148, 512, K1_SMEM>>>(x, map_w, map_b, dist_w, dist_b, bnd_w, bnd_b);
    k2<<<BB*NN, 512>>>();
    k3<<<BB*NCH3, 256, K3_SMEM>>>(x);
    k4a<<<BB*NN, 512>>>();
    k4b<<<BB, 512>>>(mask_w, mask_b, cm1_w, cm1_b, ln_g, ln_b, cm2_w, cm2_b, fin_w);
    k5<<<BB*32, 256, K5_SMEM>>>(x, fin_b, out);
}

// round 16
// speedup vs baseline: 1.0602x; 1.0602x over previous
#include <cuda_runtime.h>
#include <math.h>

#define BB 8
#define CC 512
#define NN 19
#define HW 16384
#define TOTPX (BB*HW)
#define NCH3 32   /* ocr pixel-chunks per batch */

typedef unsigned long long ull;

// ---------------- scratch (device globals; no allocation) ----------------
__device__ float g_pre[(size_t)BB*NN*HW];        // pre-softmax logits [B,N,HW]
__device__ float g_rowmax[BB*NN];
__device__ float g_rowinv[BB*NN];                // 1/sum(exp)
__device__ float g_part[(size_t)BB*NCH3*NN*CC];  // ocr partials per chunk
__device__ float g_ocr[(size_t)BB*NN*CC];        // reduced ocr
__device__ float g_weff[(size_t)BB*CC*20];       // fin_w*(1+gate), layout [b][c][20]
__device__ int   g_dummy;

__device__ __forceinline__ void fma2(ull& acc, ull a, ull b){
    asm("fma.rn.f32x2 %0, %1, %2, %0;" : "+l"(acc) : "l"(a), "l"(b));
}
__device__ __forceinline__ ull pk(float a, float b){
    ull r;
    asm("mov.b64 %0, {%1, %2};" : "=l"(r) : "r"(__float_as_uint(a)), "r"(__float_as_uint(b)));
    return r;
}
__device__ __forceinline__ float2 upk(ull v){
    unsigned int lo, hi;
    asm("mov.b64 {%0, %1}, %2;" : "=r"(lo), "=r"(hi) : "l"(v));
    float2 r; r.x = __uint_as_float(lo); r.y = __uint_as_float(hi); return r;
}
__device__ __forceinline__ unsigned smem_u32(const void* p){
    unsigned r;
    asm("{ .reg .u64 t; cvta.to.shared.u64 t, %1; cvt.u32.u64 %0, t; }" : "=r"(r) : "l"(p));
    return r;
}
__device__ __forceinline__ float sg(float v){ return 1.f/(1.f+__expf(-v)); }
__device__ __forceinline__ float chainf(float m, float dl, float bl){
    float d  = dl * sg(m);
    float bd = bl * sg(d);
    d += sg(bd);
    return m + sg(d);
}

// ---------------- dummy: shifts k3 into ncu's captured (4th) slot ----------------
__global__ void knop(int v){ if (threadIdx.x == 9999) g_dummy = v; }

// ---------------- K1 (measured 211µs): quad-split + 4px + prefetch + pointer-bump ----------------
__global__ void __launch_bounds__(512, 1) k1(const float* __restrict__ x,
    const float* __restrict__ mw, const float* __restrict__ mb,
    const float* __restrict__ dw, const float* __restrict__ db,
    const float* __restrict__ bw, const float* __restrict__ bbias)
{
    extern __shared__ float sm[];
    float* ws = sm;            // [512][64]: c-major, 4 chunks of 16 per channel
    float* bs = sm + CC*64;    // [64]
    int tid = threadIdx.x;
    for (int i = tid; i < CC*64; i += 512){
        int c = i >> 6, r = i & 63;
        int q = r >> 4, j = r & 15;
        int ii = j/3, k = j - 3*ii;
        int niq = (q < 3) ? 5 : 4;
        float v = 0.f;
        if (ii < niq && j < 15){
            int n = q*5 + ii;
            v = (k == 0) ? mw[n*CC + c] : (k == 1) ? dw[n*CC + c] : bw[n*CC + c];
        }
        ws[i] = v;
    }
    if (tid < 64){
        int q = tid >> 4, j = tid & 15;
        int ii = j/3, k = j - 3*ii;
        int niq = (q < 3) ? 5 : 4;
        float v = 0.f;
        if (ii < niq && j < 15){
            int n = q*5 + ii;
            v = (k == 0) ? mb[n] : (k == 1) ? db[n] : bbias[n];
        }
        bs[tid] = v;
    }
    __syncthreads();

    const int PER = 888;
    int start = blockIdx.x * PER;
    int end = min(start + PER, TOTPX);
    int wid = tid >> 5, lane = tid & 31;
    int g = wid >> 2, q = wid & 3;
    int niq = (q < 3) ? 5 : 4;
    const float* wq = ws + q*16;
    const float* bq = bs + q*16;

    for (int base = start; base < end; base += 512){
        int gp0 = base + g*128 + 4*lane;          // 4-aligned
        bool any = (gp0 < end);
        int gpc = any ? gp0 : start;
        int b = gpc >> 14, p = gpc & (HW-1);
        const float4* xq = reinterpret_cast<const float4*>(x + (size_t)b*CC*HW + p);
        ull A[32];                                 // [pair 0..7][px 0..3]
        #pragma unroll
        for (int j = 0; j < 32; j++) A[j] = 0ull;

        float4 xbuf[4];
        #pragma unroll
        for (int k = 0; k < 4; k++) xbuf[k] = __ldg(xq + k*4096);
        xq += 4*4096;

        const float* wc = wq;
        #pragma unroll 1
        for (int c0 = 0; c0 < CC; c0 += 4){
            bool pf = (c0 + 4 < CC);
            #pragma unroll
            for (int k = 0; k < 4; k++){
                float4 xv = xbuf[k];
                if (pf) xbuf[k] = __ldg(xq + k*4096);
                ull xd[4];
                xd[0] = pk(xv.x, xv.x); xd[1] = pk(xv.y, xv.y);
                xd[2] = pk(xv.z, xv.z); xd[3] = pk(xv.w, xv.w);
                const ulonglong2* wr = reinterpret_cast<const ulonglong2*>(wc + k*64);
                #pragma unroll
                for (int j = 0; j < 4; j++){
                    ulonglong2 w = wr[j];
                    #pragma unroll
                    for (int px = 0; px < 4; px++){
                        fma2(A[(2*j)*4 + px],   w.x, xd[px]);
                        fma2(A[(2*j+1)*4 + px], w.y, xd[px]);
                    }
                }
            }
            xq += 4*4096;
            wc += 4*64;
        }
        if (any){
            size_t ob = (size_t)b*NN*HW + p;
            #pragma unroll
            for (int i = 0; i < 5; i++){
                if (i < niq){
                    int n = q*5 + i;
                    int sm_ = 3*i, sd_ = 3*i+1, sb_ = 3*i+2;
                    float bm = bq[sm_], bd = bq[sd_], bb = bq[sb_];
                    float vout[4];
                    #pragma unroll
                    for (int px = 0; px < 4; px++){
                        float2 fm = upk(A[(sm_>>1)*4 + px]);
                        float2 fd = upk(A[(sd_>>1)*4 + px]);
                        float2 fbv = upk(A[(sb_>>1)*4 + px]);
                        float m = ((sm_&1) ? fm.y : fm.x) + bm;
                        float d = ((sd_&1) ? fd.y : fd.x) + bd;
                        float bv = ((sb_&1) ? fbv.y : fbv.x) + bb;
                        vout[px] = chainf(m, d, bv);
                    }
                    float* dst = g_pre + ob + (size_t)n*HW;
                    *reinterpret_cast<float4*>(dst) = make_float4(vout[0], vout[1], vout[2], vout[3]);
                }
            }
        }
    }
}

// ---------------- K2 v3 (measured 6.4µs): single-pass exp-sum ----------------
__global__ void __launch_bounds__(512) k2(){
    __shared__ float red[512];
    int row = blockIdx.x, tid = threadIdx.x;
    const float4* base = reinterpret_cast<const float4*>(g_pre + (size_t)row*HW);
    float sum = 0.f;
    #pragma unroll 4
    for (int i = tid; i < HW/4; i += 512){
        float4 v = base[i];
        sum += __expf(v.x) + __expf(v.y) + __expf(v.z) + __expf(v.w);
    }
    red[tid] = sum; __syncthreads();
    for (int s = 256; s > 0; s >>= 1){ if (tid < s) red[tid] += red[tid+s]; __syncthreads(); }
    if (tid == 0){ g_rowmax[row] = 0.f; g_rowinv[row] = 1.f/red[0]; }
}

// ---------------- K3 v6 (measured 112µs): cp.async double-buffered 16-px tiles ----------------
#define XR6 18
#define TPX6 16
#define NT6 32
__global__ void __launch_bounds__(256, 2) k3(const float* __restrict__ x){
    extern __shared__ float smem3[];
    float* xsbuf0 = smem3;
    float* xsbuf1 = smem3 + CC*XR6;
    ull* ppb = (ull*)(smem3 + 2*CC*XR6);        // [2][160]
    __shared__ float rm[NN], ri[NN];
    int tid = threadIdx.x;
    int b = blockIdx.x >> 5;
    int chunk = blockIdx.x & 31;
    int p0 = chunk * 512;
    if (tid < NN){ rm[tid] = g_rowmax[b*NN+tid]; ri[tid] = g_rowinv[b*NN+tid]; }
    const float* xb = x     + (size_t)b*CC*HW + p0;
    const float* pb = g_pre + (size_t)b*NN*HW + p0;
    int c0 = tid, c1 = tid + 256;
    int ppx = tid/20, ppn = tid%20;
    bool probrole = (tid < 160) && (ppn < NN);
    unsigned xs_s[2];
    xs_s[0] = smem_u32(xsbuf0);
    xs_s[1] = smem_u32(xsbuf1);
    ull acc0[20], acc1[20];
    #pragma unroll
    for (int n = 0; n < 20; n++){ acc0[n] = 0ull; acc1[n] = 0ull; }
    __syncthreads();

    #define XFILL(T, BUF) do {                                             \
        int tp_ = (T)*TPX6;                                                \
        _Pragma("unroll")                                                  \
        for (int k_ = 0; k_ < 16; k_++){                                   \
            int i_ = tid + k_*256;                                         \
            int cc_ = i_ >> 3, px2_ = (i_ & 7) * 2;                        \
            const float* src_ = xb + (size_t)cc_*HW + tp_ + px2_;          \
            unsigned dst_ = xs_s[BUF] + (unsigned)((cc_*XR6 + px2_)*4);    \
            asm volatile("cp.async.ca.shared.global [%0], [%1], 8;"        \
                         :: "r"(dst_), "l"(src_) : "memory");              \
        }                                                                  \
        asm volatile("cp.async.commit_group;" ::: "memory");               \
    } while(0)

    XFILL(0, 0);
    if (probrole){
        float2 pr = *reinterpret_cast<const float2*>(pb + (size_t)ppn*HW + 2*ppx);
        ppb[tid] = pk(__expf(pr.x - rm[ppn])*ri[ppn], __expf(pr.y - rm[ppn])*ri[ppn]);
    }
    asm volatile("cp.async.wait_group 0;" ::: "memory");
    __syncthreads();

    #pragma unroll 1
    for (int t = 0; t < NT6; t++){
        int cur = t & 1;
        float2 prnext = make_float2(0.f, 0.f);
        bool havenext = (t + 1 < NT6);
        if (havenext){
            XFILL(t+1, 1-cur);
            if (probrole)
                prnext = *reinterpret_cast<const float2*>(pb + (size_t)ppn*HW + (t+1)*TPX6 + 2*ppx);
        }
        const float* xs = cur ? xsbuf1 : xsbuf0;
        const ull* pp = ppb + cur*160;
        #pragma unroll
        for (int pxp = 0; pxp < 8; pxp++){
            ull xx0 = *reinterpret_cast<const ull*>(&xs[c0*XR6 + 2*pxp]);
            ull xx1 = *reinterpret_cast<const ull*>(&xs[c1*XR6 + 2*pxp]);
            const ulonglong2* pr = reinterpret_cast<const ulonglong2*>(&pp[pxp*20]);
            #pragma unroll
            for (int j = 0; j < 10; j++){
                ulonglong2 w = pr[j];
                fma2(acc0[2*j],   w.x, xx0); fma2(acc0[2*j+1], w.y, xx0);
                fma2(acc1[2*j],   w.x, xx1); fma2(acc1[2*j+1], w.y, xx1);
            }
        }
        if (havenext && probrole)
            ppb[(1-cur)*160 + tid] =
                pk(__expf(prnext.x - rm[ppn])*ri[ppn], __expf(prnext.y - rm[ppn])*ri[ppn]);
        asm volatile("cp.async.wait_group 0;" ::: "memory");
        __syncthreads();
    }
    #undef XFILL
    float* outp = g_part + (size_t)blockIdx.x*(NN*CC);
    #pragma unroll
    for (int n = 0; n < NN; n++){
        float2 v0 = upk(acc0[n]), v1 = upk(acc1[n]);
        outp[n*CC + c0] = v0.x + v0.y;
        outp[n*CC + c1] = v1.x + v1.y;
    }
}

// ---------------- K4a (measured 6.8µs): reduce ocr partials ----------------
__global__ void __launch_bounds__(512) k4a(){
    int b = blockIdx.x / NN, n = blockIdx.x % NN, c = threadIdx.x;
    float s = 0.f;
    #pragma unroll 8
    for (int ch = 0; ch < NCH3; ch++)
        s += g_part[((size_t)(b*NCH3 + ch))*(NN*CC) + n*CC + c];
    g_ocr[((size_t)b*NN + n)*CC + c] = s;
}

// ---------------- block sum helper ----------------
__device__ __forceinline__ float blockSum(float v, float* red, int tid){
    __syncthreads();
    #pragma unroll
    for (int o = 16; o; o >>= 1) v += __shfl_xor_sync(0xffffffffu, v, o);
    if ((tid & 31) == 0) red[tid >> 5] = v;
    __syncthreads();
    if (tid < 32){
        float r = (tid < 16) ? red[tid] : 0.f;
        #pragma unroll
        for (int o = 8; o; o >>= 1) r += __shfl_xor_sync(0xffffffffu, r, o);
        if (tid == 0) red[0] = r;
    }
    __syncthreads();
    return red[0];
}

// ---------------- K4b: att pool + MLP gate -> g_weff ----------------
__global__ void __launch_bounds__(512) k4b(
    const float* __restrict__ mask_w, const float* __restrict__ mask_b,
    const float* __restrict__ cm1_w,  const float* __restrict__ cm1_b,
    const float* __restrict__ ln_g,   const float* __restrict__ ln_b,
    const float* __restrict__ cm2_w,  const float* __restrict__ cm2_b,
    const float* __restrict__ fin_w)
{
    __shared__ float ocr[NN][CC];
    __shared__ float mws[CC];
    __shared__ float ctx[CC];
    __shared__ float h[CC];
    __shared__ float attw[NN];
    __shared__ float red[16];
    __shared__ float stat[2];
    int b = blockIdx.x, tid = threadIdx.x;
    int wid = tid >> 5, lane = tid & 31;
    mws[tid] = mask_w[tid];
    for (int n = 0; n < NN; n++)
        ocr[n][tid] = g_ocr[((size_t)b*NN + n)*CC + tid];
    __syncthreads();
    for (int n = wid; n < NN; n += 16){
        float s = 0.f;
        #pragma unroll
        for (int l = lane; l < CC; l += 32) s += ocr[n][l]*mws[l];
        #pragma unroll
        for (int o = 16; o; o >>= 1) s += __shfl_xor_sync(0xffffffffu, s, o);
        if (lane == 0) attw[n] = s;
    }
    __syncthreads();
    if (tid == 0){
        float mbv = mask_b[0];
        float amax = -3.4e38f;
        for (int n = 0; n < NN; n++) amax = fmaxf(amax, attw[n] + mbv);
        float s = 0.f;
        for (int n = 0; n < NN; n++){ float e = __expf(attw[n] + mbv - amax); attw[n] = e; s += e; }
        float inv = 1.f/s;
        for (int n = 0; n < NN; n++) attw[n] *= inv;
    }
    __syncthreads();
    float cv = 0.f;
    #pragma unroll
    for (int n = 0; n < NN; n++) cv += ocr[n][tid]*attw[n];
    ctx[tid] = cv; __syncthreads();
    float acc = cm1_b[tid];
    {
        const float4* w1 = reinterpret_cast<const float4*>(cm1_w + (size_t)tid*CC);
        const float4* cx = reinterpret_cast<const float4*>(ctx);
        #pragma unroll 4
        for (int q = 0; q < CC/4; q++){
            float4 wv = __ldg(w1 + q); float4 xv = cx[q];
            acc += wv.x*xv.x + wv.y*xv.y + wv.z*xv.z + wv.w*xv.w;
        }
    }
    float mu = blockSum(acc, red, tid) * (1.f/CC);
    if (tid == 0) stat[0] = mu;
    float dv = acc - mu;
    float var = blockSum(dv*dv, red, tid) * (1.f/CC);
    float tt = dv*rsqrtf(var + 1e-5f)*ln_g[tid] + ln_b[tid];
    h[tid] = fmaxf(tt, 0.f);
    __syncthreads();
    float acc2 = cm2_b[tid];
    {
        const float4* w2 = reinterpret_cast<const float4*>(cm2_w + (size_t)tid*CC);
        const float4* hh = reinterpret_cast<const float4*>(h);
        #pragma unroll 4
        for (int q = 0; q < CC/4; q++){
            float4 wv = __ldg(w2 + q); float4 xv = hh[q];
            acc2 += wv.x*xv.x + wv.y*xv.y + wv.z*xv.z + wv.w*xv.w;
        }
    }
    float scale = 1.f + 1.f/(1.f+__expf(-acc2));   // 1 + gate
    float* wo = g_weff + (size_t)b*CC*20 + (size_t)tid*20;
    #pragma unroll
    for (int n = 0; n < NN; n++) wo[n] = fin_w[n*CC + tid]*scale;
    wo[19] = 0.f;
}

// ---------------- K5 v4b (kept from R15, est ~110µs): warp-pair n-split, 8-deep prefetch ----------------
__global__ void __launch_bounds__(256, 2) k5(const float* __restrict__ x,
                                             const float* __restrict__ fin_b,
                                             float* __restrict__ out)
{
    extern __shared__ float sm5[];
    float* ws5 = sm5;             // [512][24]
    float* fbs = sm5 + CC*24;     // [24]
    int tid = threadIdx.x;
    int b = blockIdx.x >> 5;
    int chunk = blockIdx.x & 31;
    const float* wsrc = g_weff + (size_t)b*CC*20;
    for (int i = tid; i < CC*24; i += 256){
        int c = i/24, r = i%24;
        int h = r/12, j = r%12;
        int n = 10*h + j;
        ws5[i] = (j < 10 && n < 19) ? wsrc[c*20 + n] : 0.f;
    }
    if (tid < 24) fbs[tid] = (tid < 19) ? fin_b[tid] : 0.f;
    __syncthreads();

    int wid = tid >> 5, lane = tid & 31;
    int u = wid >> 1, h = wid & 1;
    int p = chunk*512 + u*128 + 4*lane;
    const float4* xq = reinterpret_cast<const float4*>(x + (size_t)b*CC*HW + p);
    ull acc[20];                                   // [pair 0..4][px 0..3]
    #pragma unroll
    for (int j = 0; j < 20; j++) acc[j] = 0ull;

    float4 xbuf[8];
    #pragma unroll
    for (int k = 0; k < 8; k++) xbuf[k] = __ldg(xq + k*4096);
    xq += 8*4096;

    const float* wc = ws5 + h*12;
    #pragma unroll 1
    for (int c0 = 0; c0 < CC; c0 += 8){
        bool pf = (c0 + 8 < CC);
        #pragma unroll
        for (int k = 0; k < 8; k++){
            float4 xv = xbuf[k];
            if (pf) xbuf[k] = __ldg(xq + k*4096);
            ull xd[4];
            xd[0] = pk(xv.x, xv.x); xd[1] = pk(xv.y, xv.y);
            xd[2] = pk(xv.z, xv.z); xd[3] = pk(xv.w, xv.w);
            const ulonglong2* wr = reinterpret_cast<const ulonglong2*>(wc + k*24);
            ulonglong2 w01 = wr[0];
            ulonglong2 w23 = wr[1];
            ulonglong2 w45 = wr[2];
            #pragma unroll
            for (int px = 0; px < 4; px++){
                fma2(acc[0*4 + px], w01.x, xd[px]);
                fma2(acc[1*4 + px], w01.y, xd[px]);
                fma2(acc[2*4 + px], w23.x, xd[px]);
                fma2(acc[3*4 + px], w23.y, xd[px]);
                fma2(acc[4*4 + px], w45.x, xd[px]);
            }
        }
        xq += 8*4096;
        wc += 8*24;
    }
    size_t ob = (size_t)b*NN*HW + p;
    #pragma unroll
    for (int pj = 0; pj < 5; pj++){
        int n0 = 10*h + 2*pj, n1 = n0 + 1;
        float v0[4], v1[4];
        #pragma unroll
        for (int px = 0; px < 4; px++){
            float2 f = upk(acc[pj*4 + px]);
            v0[px] = f.x + fbs[n0];
            v1[px] = f.y + ((n1 < 19) ? fbs[n1] : 0.f);
        }
        *reinterpret_cast<float4*>(out + ob + (size_t)n0*HW) = make_float4(v0[0], v0[1], v0[2], v0[3]);
        if (n1 < 19)
            *reinterpret_cast<float4*>(out + ob + (size_t)n1*HW) = make_float4(v1[0], v1[1], v1[2], v1[3]);
    }
}

extern "C" void kernel_launch(void* const* d_in, const int* in_sizes, int n_in,
                              void* d_out, int out_size) {
    const float* x      = (const float*)d_in[0];
    const float* map_w  = (const float*)d_in[1];
    const float* map_b  = (const float*)d_in[2];
    const float* dist_w = (const float*)d_in[3];
    const float* dist_b = (const float*)d_in[4];
    const float* bnd_w  = (const float*)d_in[5];
    const float* bnd_b  = (const float*)d_in[6];
    const float* mask_w = (const float*)d_in[7];
    const float* mask_b = (const float*)d_in[8];
    const float* cm1_w  = (const float*)d_in[9];
    const float* cm1_b  = (const float*)d_in[10];
    const float* ln_g   = (const float*)d_in[11];
    const float* ln_b   = (const float*)d_in[12];
    const float* cm2_w  = (const float*)d_in[13];
    const float* cm2_b  = (const float*)d_in[14];
    const float* fin_w  = (const float*)d_in[15];
    const float* fin_b  = (const float*)d_in[16];
    float* out = (float*)d_out;

    const int K1_SMEM = (CC*64 + 64)*4;                        // 131328 B
    const int K3_SMEM = (2*CC*XR6)*4 + 2*160*8;                // 76288 B
    const int K5_SMEM = (CC*24 + 24)*4;                        // 49248 B
    cudaFuncSetAttribute(k1, cudaFuncAttributeMaxDynamicSharedMemorySize, K1_SMEM);
    cudaFuncSetAttribute(k3, cudaFuncAttributeMaxDynamicSharedMemorySize, K3_SMEM);
    cudaFuncSetAttribute(k5, cudaFuncAttributeMaxDynamicSharedMemorySize, K5_SMEM);

    // one no-op: k3 lands in ncu's captured (4th) launch slot
    knop<<<1, 32>>>(0);

    k1<<<148, 512, K1_SMEM>>>(x, map_w, map_b, dist_w, dist_b, bnd_w, bnd_b);
    k2<<<BB*NN, 512>>>();
    k3<<<BB*NCH3, 256, K3_SMEM>>>(x);
    k4a<<<BB*NN, 512>>>();
    k4b<<<BB, 512>>>(mask_w, mask_b, cm1_w, cm1_b, ln_g, ln_b, cm2_w, cm2_b, fin_w);
    k5<<<BB*32, 256, K5_SMEM>>>(x, fin_b, out);
}